// round 1
// baseline (speedup 1.0000x reference)
#include <cuda_runtime.h>
#include <math.h>

#define BG    128
#define NPG0  512
#define ETOT  524288
#define NTMAX 65536
#define KK1   256
#define KK2   128
#define KK3   64

// ---------------- scratch (device globals: no allocations allowed) ----------
__device__ float g_t[(size_t)NTMAX * 128];     // x @ W
__device__ float g_h[(size_t)NTMAX * 128];     // gcn output (post-relu)
__device__ float g_x1[(size_t)BG * KK1 * 128]; // stage1 pooled features
__device__ float g_x2[(size_t)BG * KK2 * 128];
__device__ float g_x3[(size_t)BG * KK3 * 128];
__device__ float g_deg[NTMAX];
__device__ float g_dinv[NTMAX];
__device__ float g_score[NTMAX];
__device__ float g_sagg[NTMAX];
__device__ int   g_newidx[NTMAX];
__device__ int   g_src[ETOT];
__device__ int   g_dst[ETOT];
__device__ float g_emask[ETOT];
__device__ int   g_perm[BG * KK1];
__device__ float g_tanhv[BG * KK1];

// ---------------- kernels ---------------------------------------------------

__global__ void k_fill_deg(int NT) {
    int i = blockIdx.x * blockDim.x + threadIdx.x;
    if (i < NT) g_deg[i] = 1.0f;   // self-loop
}

__global__ void k_deg(const int* __restrict__ dst, const float* __restrict__ emask) {
    int e = blockIdx.x * blockDim.x + threadIdx.x;
    if (e >= ETOT) return;
    float m = emask ? emask[e] : 1.0f;
    if (m != 0.0f) atomicAdd(&g_deg[dst[e]], m);
}

__global__ void k_dinv(int NT) {
    int i = blockIdx.x * blockDim.x + threadIdx.x;
    if (i < NT) g_dinv[i] = rsqrtf(g_deg[i]);
}

// t[NT,128] = X[NT,128] @ W[128,128].  W staged in 64KB smem, 4 rows per warp.
__global__ void k_gemm(const float* __restrict__ X, const float* __restrict__ W, int NT) {
    extern __shared__ float Wsh[];  // 128*128
    for (int i = threadIdx.x; i < 128 * 128; i += blockDim.x) Wsh[i] = W[i];
    __syncthreads();
    int warp = threadIdx.x >> 5, lane = threadIdx.x & 31;
    int row0 = (blockIdx.x * 8 + warp) * 4;
    if (row0 >= NT) return;
    const float* x0 = X + (size_t)row0 * 128;
    float acc[4][4] = {};
#pragma unroll
    for (int kb = 0; kb < 4; kb++) {
        float xk0 = x0[0 * 128 + kb * 32 + lane];
        float xk1 = x0[1 * 128 + kb * 32 + lane];
        float xk2 = x0[2 * 128 + kb * 32 + lane];
        float xk3 = x0[3 * 128 + kb * 32 + lane];
#pragma unroll
        for (int j = 0; j < 32; j++) {
            float4 w4 = *(const float4*)&Wsh[(kb * 32 + j) * 128 + lane * 4];
            float a0 = __shfl_sync(0xffffffffu, xk0, j);
            float a1 = __shfl_sync(0xffffffffu, xk1, j);
            float a2 = __shfl_sync(0xffffffffu, xk2, j);
            float a3 = __shfl_sync(0xffffffffu, xk3, j);
            acc[0][0] += a0 * w4.x; acc[0][1] += a0 * w4.y; acc[0][2] += a0 * w4.z; acc[0][3] += a0 * w4.w;
            acc[1][0] += a1 * w4.x; acc[1][1] += a1 * w4.y; acc[1][2] += a1 * w4.z; acc[1][3] += a1 * w4.w;
            acc[2][0] += a2 * w4.x; acc[2][1] += a2 * w4.y; acc[2][2] += a2 * w4.z; acc[2][3] += a2 * w4.w;
            acc[3][0] += a3 * w4.x; acc[3][1] += a3 * w4.y; acc[3][2] += a3 * w4.z; acc[3][3] += a3 * w4.w;
        }
    }
#pragma unroll
    for (int r = 0; r < 4; r++) {
        float4 o = make_float4(acc[r][0], acc[r][1], acc[r][2], acc[r][3]);
        *(float4*)&g_t[(size_t)(row0 + r) * 128 + lane * 4] = o;
    }
}

// h = dinv^2 * t + b   (self-loop term + bias, before edge scatter)
__global__ void k_self(const float* __restrict__ bvec, int NT) {
    int idx = blockIdx.x * blockDim.x + threadIdx.x;  // over NT*32 float4
    if (idx >= NT * 32) return;
    int n = idx >> 5, c4 = (idx & 31) * 4;
    float di = g_dinv[n]; float s = di * di;
    float4 t = *(const float4*)&g_t[(size_t)n * 128 + c4];
    float4 b = *(const float4*)&bvec[c4];
    float4 o = make_float4(t.x * s + b.x, t.y * s + b.y, t.z * s + b.z, t.w * s + b.w);
    *(float4*)&g_h[(size_t)n * 128 + c4] = o;
}

// h[dst] += dinv[src]*dinv[dst]*m * t[src]   (one warp per edge, v4 red atomics)
__global__ void k_edge_agg(const int* __restrict__ src, const int* __restrict__ dst,
                           const float* __restrict__ emask) {
    int w = (blockIdx.x * blockDim.x + threadIdx.x) >> 5;
    int lane = threadIdx.x & 31;
    if (w >= ETOT) return;
    float m = emask ? emask[w] : 1.0f;
    if (m == 0.0f) return;
    int s = src[w], d = dst[w];
    float norm = g_dinv[s] * g_dinv[d] * m;
    float4 t = *(const float4*)&g_t[(size_t)s * 128 + lane * 4];
    float* p = &g_h[(size_t)d * 128 + lane * 4];
    asm volatile("red.global.add.v4.f32 [%0], {%1,%2,%3,%4};"
                 :: "l"(p), "f"(t.x * norm), "f"(t.y * norm), "f"(t.z * norm), "f"(t.w * norm)
                 : "memory");
}

__global__ void k_relu(int NT) {
    int idx = blockIdx.x * blockDim.x + threadIdx.x;
    if (idx >= NT * 32) return;
    float4* p = (float4*)&g_h[(size_t)idx * 4];
    float4 v = *p;
    v.x = fmaxf(v.x, 0.f); v.y = fmaxf(v.y, 0.f); v.z = fmaxf(v.z, 0.f); v.w = fmaxf(v.w, 0.f);
    *p = v;
}

// score = h @ Ws  (warp per node)
__global__ void k_sdot(const float* __restrict__ Wsv, int NT) {
    int w = (blockIdx.x * blockDim.x + threadIdx.x) >> 5;
    int lane = threadIdx.x & 31;
    if (w >= NT) return;
    float4 h4 = *(const float4*)&g_h[(size_t)w * 128 + lane * 4];
    float4 w4 = *(const float4*)&Wsv[lane * 4];
    float v = h4.x * w4.x + h4.y * w4.y + h4.z * w4.z + h4.w * w4.w;
#pragma unroll
    for (int o = 16; o; o >>= 1) v += __shfl_xor_sync(0xffffffffu, v, o);
    if (lane == 0) g_score[w] = v;
}

__global__ void k_sagg_init(const float* __restrict__ bsv, int NT) {
    int i = blockIdx.x * blockDim.x + threadIdx.x;
    if (i >= NT) return;
    float di = g_dinv[i];
    g_sagg[i] = di * di * g_score[i] + bsv[0];
}

__global__ void k_sagg_edge(const int* __restrict__ src, const int* __restrict__ dst,
                            const float* __restrict__ emask) {
    int e = blockIdx.x * blockDim.x + threadIdx.x;
    if (e >= ETOT) return;
    float m = emask ? emask[e] : 1.0f;
    if (m == 0.0f) return;
    int s = src[e], d = dst[e];
    atomicAdd(&g_sagg[d], g_dinv[s] * g_dinv[d] * m * g_score[s]);
}

// per-graph top-k via bitonic sort of (negated score, idx); one block per graph
__global__ void k_topk(int n_pg, int kk) {
    __shared__ float vals[512];
    __shared__ int   idxs[512];
    int g = blockIdx.x, i = threadIdx.x;   // blockDim == n_pg (power of 2)
    int base = g * n_pg;
    vals[i] = -g_sagg[base + i];
    idxs[i] = i;
    g_newidx[base + i] = -1;
    __syncthreads();
    for (int k2 = 2; k2 <= n_pg; k2 <<= 1) {
        for (int j = k2 >> 1; j > 0; j >>= 1) {
            int ixj = i ^ j;
            if (ixj > i) {
                bool up = ((i & k2) == 0);   // ascending on negated -> top scores first
                float vi = vals[i], vj = vals[ixj];
                bool sw = up ? (vi > vj) : (vi < vj);
                if (sw) {
                    vals[i] = vj; vals[ixj] = vi;
                    int t = idxs[i]; idxs[i] = idxs[ixj]; idxs[ixj] = t;
                }
            }
            __syncthreads();
        }
    }
    if (i < kk) {
        int node = base + idxs[i];
        int nid = g * kk + i;
        g_newidx[node] = nid;
        g_perm[nid] = node;
        g_tanhv[nid] = tanhf(-vals[i]);
    }
}

__global__ void k_gather(float* __restrict__ xout, int M) {
    int idx = blockIdx.x * blockDim.x + threadIdx.x;  // over M*32 float4
    if (idx >= M * 32) return;
    int row = idx >> 5, c4 = (idx & 31) * 4;
    float sc = g_tanhv[row];
    float4 v = *(const float4*)&g_h[(size_t)g_perm[row] * 128 + c4];
    float4 o = make_float4(v.x * sc, v.y * sc, v.z * sc, v.w * sc);
    *(float4*)&xout[(size_t)row * 128 + c4] = o;
}

__global__ void k_remap(const int* __restrict__ src_in, const int* __restrict__ dst_in,
                        const float* __restrict__ emask_in) {
    int e = blockIdx.x * blockDim.x + threadIdx.x;
    if (e >= ETOT) return;
    float m = emask_in ? emask_in[e] : 1.0f;
    int s = src_in[e], d = dst_in[e];
    int ns = g_newidx[s], nd = g_newidx[d];
    bool valid = (ns >= 0) && (nd >= 0);
    g_src[e] = valid ? ns : 0;
    g_dst[e] = valid ? nd : 0;
    g_emask[e] = (valid && m != 0.0f) ? 1.0f : 0.0f;
}

// per-graph [max | mean] readout, accumulated into d_out
__global__ void k_readout(const float* __restrict__ x, int kk, float* __restrict__ out, int accFlag) {
    int g = blockIdx.x, c = threadIdx.x;  // 128 threads
    float mx = -3.402823466e38f, sm = 0.f;
    const float* p = x + (size_t)g * kk * 128 + c;
    for (int j = 0; j < kk; j++) {
        float v = p[(size_t)j * 128];
        mx = fmaxf(mx, v);
        sm += v;
    }
    float mean = sm / (float)kk;
    if (accFlag) {
        out[g * 256 + c]       += mx;
        out[g * 256 + 128 + c] += mean;
    } else {
        out[g * 256 + c]       = mx;
        out[g * 256 + 128 + c] = mean;
    }
}

// ---------------- host driver ----------------------------------------------

static void run_stage(const float* xin, int n_pg, int kk,
                      const float* W, const float* bvec, const float* Wsv, const float* bsv,
                      const int* src, const int* dst, const float* emask,
                      float* xout, float* out, int accFlag, int doRemap) {
    int NT = BG * n_pg;
    k_fill_deg<<<NT / 256, 256>>>(NT);
    k_deg<<<ETOT / 256, 256>>>(dst, emask);
    k_dinv<<<NT / 256, 256>>>(NT);
    k_gemm<<<NT / 32, 256, 65536>>>(xin, W, NT);
    k_self<<<NT / 8, 256>>>(bvec, NT);
    k_edge_agg<<<ETOT / 8, 256>>>(src, dst, emask);
    k_relu<<<NT / 8, 256>>>(NT);
    k_sdot<<<NT / 8, 256>>>(Wsv, NT);
    k_sagg_init<<<(NT + 255) / 256, 256>>>(bsv, NT);
    k_sagg_edge<<<ETOT / 256, 256>>>(src, dst, emask);
    k_topk<<<BG, n_pg>>>(n_pg, kk);
    int M = BG * kk;
    k_gather<<<M / 8, 256>>>(xout, M);
    if (doRemap) k_remap<<<ETOT / 256, 256>>>(src, dst, emask);
    k_readout<<<BG, 128>>>(xout, kk, out, accFlag);
}

extern "C" void kernel_launch(void* const* d_in, const int* in_sizes, int n_in,
                              void* d_out, int out_size) {
    (void)in_sizes; (void)n_in; (void)out_size;
    const float* x   = (const float*)d_in[0];
    const int*   ei  = (const int*)d_in[1];
    const float* W1  = (const float*)d_in[3];
    const float* b1  = (const float*)d_in[4];
    const float* Ws1 = (const float*)d_in[5];
    const float* bs1 = (const float*)d_in[6];
    const float* W2  = (const float*)d_in[7];
    const float* b2  = (const float*)d_in[8];
    const float* Ws2 = (const float*)d_in[9];
    const float* bs2 = (const float*)d_in[10];
    const float* W3  = (const float*)d_in[11];
    const float* b3  = (const float*)d_in[12];
    const float* Ws3 = (const float*)d_in[13];
    const float* bs3 = (const float*)d_in[14];
    float* out = (float*)d_out;

    cudaFuncSetAttribute(k_gemm, cudaFuncAttributeMaxDynamicSharedMemorySize, 65536);

    float *px1, *px2, *px3;
    int *psrc, *pdst;
    float *pmask;
    cudaGetSymbolAddress((void**)&px1, g_x1);
    cudaGetSymbolAddress((void**)&px2, g_x2);
    cudaGetSymbolAddress((void**)&px3, g_x3);
    cudaGetSymbolAddress((void**)&psrc, g_src);
    cudaGetSymbolAddress((void**)&pdst, g_dst);
    cudaGetSymbolAddress((void**)&pmask, g_emask);

    const int* src0 = ei;
    const int* dst0 = ei + ETOT;

    // Stage 1: N=512 -> K1=256
    run_stage(x, NPG0, KK1, W1, b1, Ws1, bs1, src0, dst0, nullptr, px1, out, /*acc=*/0, /*remap=*/1);
    // Stage 2: K1=256 -> K2=128
    run_stage(px1, KK1, KK2, W2, b2, Ws2, bs2, psrc, pdst, pmask, px2, out, /*acc=*/1, /*remap=*/1);
    // Stage 3: K2=128 -> K3=64 (edges no longer needed afterwards)
    run_stage(px2, KK2, KK3, W3, b3, Ws3, bs3, psrc, pdst, pmask, px3, out, /*acc=*/1, /*remap=*/0);
}